// round 6
// baseline (speedup 1.0000x reference)
#include <cuda_runtime.h>
#include <cuda_bf16.h>

#define BATCH 64
#define NUM_SPEC 8
#define VOCAB 128000
#define ROWS (BATCH * NUM_SPEC)   // 512
#define V4 (VOCAB / 4)            // 32000 float4 per row
#define THREADS 256
#define UNROLL 8
// per-thread totals: 32000/256 = 125 float4 = 15 batches of 8 + 5 tail
#define FULL_BATCHES 15
#define TAIL 5

// Scratch for argmax winners (device global; no allocation allowed).
__device__ int g_target_tok[ROWS];

// ---------------------------------------------------------------------------
// Kernel 1: per-row argmax over 128000 fp32 logits.
// One CTA per (batch, spec) row. Batched float4 loads (8 independent loads
// issued before any compare) to maximize MLP. Strict > keeps the FIRST max
// within a thread; cross-thread reduce breaks ties toward smaller index
// (matches jnp.argmax first-occurrence semantics).
// ---------------------------------------------------------------------------
__global__ void __launch_bounds__(THREADS) argmax_rows_kernel(
    const float* __restrict__ logits)
{
    const int row = blockIdx.x;
    const float4* __restrict__ p =
        reinterpret_cast<const float4*>(logits + (size_t)row * VOCAB);

    float best = -3.402823466e+38f;
    int bidx = 0;

    int base = threadIdx.x;
    for (int m = 0; m < FULL_BATCHES; m++) {
        float4 v[UNROLL];
        #pragma unroll
        for (int k = 0; k < UNROLL; k++) {
            v[k] = p[base + k * THREADS];
        }
        #pragma unroll
        for (int k = 0; k < UNROLL; k++) {
            int e = (base + k * THREADS) * 4;
            if (v[k].x > best) { best = v[k].x; bidx = e; }
            if (v[k].y > best) { best = v[k].y; bidx = e + 1; }
            if (v[k].z > best) { best = v[k].z; bidx = e + 2; }
            if (v[k].w > best) { best = v[k].w; bidx = e + 3; }
        }
        base += UNROLL * THREADS;
    }
    // Tail: 5 more float4 per thread.
    {
        float4 v[TAIL];
        #pragma unroll
        for (int k = 0; k < TAIL; k++) {
            v[k] = p[base + k * THREADS];
        }
        #pragma unroll
        for (int k = 0; k < TAIL; k++) {
            int e = (base + k * THREADS) * 4;
            if (v[k].x > best) { best = v[k].x; bidx = e; }
            if (v[k].y > best) { best = v[k].y; bidx = e + 1; }
            if (v[k].z > best) { best = v[k].z; bidx = e + 2; }
            if (v[k].w > best) { best = v[k].w; bidx = e + 3; }
        }
    }

    // Block reduction with first-index tie-break.
    __shared__ float svals[THREADS];
    __shared__ int   sidx[THREADS];
    svals[threadIdx.x] = best;
    sidx[threadIdx.x]  = bidx;
    __syncthreads();

    for (int off = THREADS / 2; off > 0; off >>= 1) {
        if (threadIdx.x < off) {
            float ov = svals[threadIdx.x + off];
            int   oi = sidx[threadIdx.x + off];
            float mv = svals[threadIdx.x];
            int   mi = sidx[threadIdx.x];
            if (ov > mv || (ov == mv && oi < mi)) {
                svals[threadIdx.x] = ov;
                sidx[threadIdx.x]  = oi;
            }
        }
        __syncthreads();
    }

    if (threadIdx.x == 0) {
        g_target_tok[row] = sidx[0];
    }
}

// ---------------------------------------------------------------------------
// Kernel 2: accept/reject prefix logic, one thread per batch row.
// Inputs int32 (JAX demotes int64 without x64); OUTPUT IS FLOAT32:
// the harness's __output__ dtype is fp32 (int -1 bits would read as NaN,
// which exactly matched the observed rel_err=nan).
// Output (float32):
//   [0 .. 576)   output_token_ids    [64][9]
//   [576 .. 640) num_rejected_tokens [64]
//   [640 .. 704) last_token_ids      [64]
// ---------------------------------------------------------------------------
__global__ void epilogue_kernel(
    const int* __restrict__ draft,    // [64][8]
    const int* __restrict__ bonus,    // [64][1]
    float* __restrict__ out)
{
    const int b = threadIdx.x;
    if (b >= BATCH) return;

    int tt[NUM_SPEC];
    int num_accept = 0;
    bool prefix = true;
    #pragma unroll
    for (int j = 0; j < NUM_SPEC; j++) {
        tt[j] = g_target_tok[b * NUM_SPEC + j];
        if (prefix) {
            if (draft[b * NUM_SPEC + j] == tt[j]) num_accept++;
            else prefix = false;
        }
    }

    const bool all_acc = (num_accept == NUM_SPEC);
    const int keep_cnt = all_acc ? NUM_SPEC : (num_accept + 1);

    #pragma unroll
    for (int j = 0; j < NUM_SPEC; j++) {
        out[b * (NUM_SPEC + 1) + j] = (j < keep_cnt) ? (float)tt[j] : -1.0f;
    }
    out[b * (NUM_SPEC + 1) + NUM_SPEC] = all_acc ? (float)bonus[b] : -1.0f;

    out[BATCH * (NUM_SPEC + 1) + b] = (float)(NUM_SPEC - num_accept);

    float last = all_acc ? (float)bonus[b] : (float)tt[num_accept];
    out[BATCH * (NUM_SPEC + 1) + BATCH + b] = last;
}

extern "C" void kernel_launch(void* const* d_in, const int* in_sizes, int n_in,
                              void* d_out, int out_size)
{
    const float* logits = (const float*)d_in[0];
    const int*   draft  = (const int*)d_in[1];
    const int*   bonus  = (const int*)d_in[2];
    float*       out    = (float*)d_out;

    argmax_rows_kernel<<<ROWS, THREADS>>>(logits);
    epilogue_kernel<<<1, BATCH>>>(draft, bonus, out);
}